// round 13
// baseline (speedup 1.0000x reference)
#include <cuda_runtime.h>
#include <cuda_fp16.h>
#include <math.h>

// ---------------- problem constants ----------------
#define Bsz   64
#define Nn    256
#define CT    3
#define HID   256
#define HEADS 4
#define Ch    64
#define Eg    8192
#define F_IN  (Nn*CT)
#define ROWS  (Bsz*Nn)
#define NEGS  0.2f
#define EPSBN 1e-5f

// ---------------- scratch ----------------
__device__ float  g_h [ROWS*HID];
__device__ float  g_h2[ROWS*HID];
__device__ float  g_xl[ROWS*HID];
__device__ float  g_xr[ROWS*HID];
__device__ int    g_off[Nn+1];
__device__ int    g_srce[Eg];
__device__ int    g_dste[Eg];
#define WT_W1  0
#define WT_L0  (F_IN*HID)
#define WT_R0  (F_IN*HID + HID*HID)
#define WT_L1  (F_IN*HID + 2*HID*HID)
#define WT_R1  (F_IN*HID + 3*HID*HID)
#define WT_TOT (F_IN*HID + 4*HID*HID)
__device__ __half g_wthi[WT_TOT];
__device__ __half g_wtlo[WT_TOT];

__device__ __forceinline__ float gelu_exact(float x) { return x * normcdff(x); }

__device__ __forceinline__ void mma_f16(float* c, const unsigned* a, const unsigned* b) {
    asm("mma.sync.aligned.m16n8k16.row.col.f32.f16.f16.f32 "
        "{%0,%1,%2,%3},{%4,%5,%6,%7},{%8,%9},{%0,%1,%2,%3};"
        : "+f"(c[0]), "+f"(c[1]), "+f"(c[2]), "+f"(c[3])
        : "r"(a[0]), "r"(a[1]), "r"(a[2]), "r"(a[3]), "r"(b[0]), "r"(b[1]));
}

__device__ __forceinline__ void cp16(unsigned saddr, const void* g) {
    asm volatile("cp.async.cg.shared.global [%0], [%1], 16;" :: "r"(saddr), "l"(g));
}

__device__ __forceinline__ void split4(float4 f, unsigned& h0, unsigned& h1,
                                       unsigned& l0, unsigned& l1) {
    __half2 a = __float22half2_rn(make_float2(f.x, f.y));
    __half2 b = __float22half2_rn(make_float2(f.z, f.w));
    float2 fa = __half22float2(a);
    float2 fb = __half22float2(b);
    __half2 c = __float22half2_rn(make_float2(f.x - fa.x, f.y - fa.y));
    __half2 d = __float22half2_rn(make_float2(f.z - fb.x, f.w - fb.y));
    h0 = *(unsigned*)&a; h1 = *(unsigned*)&b;
    l0 = *(unsigned*)&c; l1 = *(unsigned*)&d;
}

// ---------------- deterministic CSR build (srce + dste) ----------------
__global__ __launch_bounds__(256)
void build_csr_kernel(const int* __restrict__ ei,
                      int* __restrict__ off,
                      int* __restrict__ srce, int* __restrict__ dste) {
    __shared__ int hist[8][Nn];
    __shared__ int s_loc[Eg];
    __shared__ int s_off[Nn+1];

    const int tid  = threadIdx.x;
    const int w    = tid >> 5;
    const int lane = tid & 31;
    const int* srcA = ei;
    const int* dstA = ei + Eg;

    for (int i = tid; i < 8 * Nn; i += 256) ((int*)hist)[i] = 0;
    __syncthreads();

    const int base = w * 1024;
#pragma unroll 1
    for (int g = 0; g < 32; g++) {
        const int e = base + g * 32 + lane;
        const int d = dstA[e];
        unsigned mask = __match_any_sync(0xffffffffu, d);
        int leader = __ffs(mask) - 1;
        int rank   = __popc(mask & ((1u << lane) - 1u));
        int cur    = hist[w][d];
        s_loc[e]   = cur + rank;
        __syncwarp();
        if (lane == leader) hist[w][d] = cur + __popc(mask);
        __syncwarp();
    }
    __syncthreads();

    __shared__ int tot[Nn];
    if (tid < Nn) {
        int run = 0;
#pragma unroll
        for (int ww = 0; ww < 8; ww++) {
            int c = hist[ww][tid];
            hist[ww][tid] = run;
            run += c;
        }
        tot[tid] = run;
    }
    __syncthreads();
    if (tid == 0) {
        int run = 0;
        for (int n = 0; n < Nn; n++) { s_off[n] = run; run += tot[n]; }
        s_off[Nn] = run;
    }
    __syncthreads();

    if (tid < Nn) off[tid] = s_off[tid];
    if (tid == 0) off[Nn] = s_off[Nn];

    for (int e = tid; e < Eg; e += 256) {
        const int d  = dstA[e];
        const int we = e >> 10;
        const int pos = s_off[d] + hist[we][d] + s_loc[e];
        srce[pos] = srcA[e];
        dste[pos] = d;
    }
}

// ---------------- fused weight transpose+split ----------------
__global__ __launch_bounds__(256)
void convT_all_kernel(const float* __restrict__ W1,
                      const float* __restrict__ Wl0, const float* __restrict__ Wr0,
                      const float* __restrict__ Wl1, const float* __restrict__ Wr1,
                      __half* __restrict__ Thi, __half* __restrict__ Tlo) {
    int idx = blockIdx.x * 256 + threadIdx.x;
    if (idx >= WT_TOT) return;
    const float* W; int Kd, loc;
    if (idx < WT_L0)      { W = W1;  Kd = F_IN; loc = idx - WT_W1; }
    else if (idx < WT_R0) { W = Wl0; Kd = HID;  loc = idx - WT_L0; }
    else if (idx < WT_L1) { W = Wr0; Kd = HID;  loc = idx - WT_R0; }
    else if (idx < WT_R1) { W = Wl1; Kd = HID;  loc = idx - WT_L1; }
    else                  { W = Wr1; Kd = HID;  loc = idx - WT_R1; }
    int n = loc / Kd, k = loc % Kd;
    float f = W[(size_t)k * HID + n];
    __half h = __float2half_rn(f);
    Thi[idx] = h;
    Tlo[idx] = __float2half_rn(f - __half2float(h));
}

// ---------------- GEMM (round-9 proven): fp32 A loader-split, fp16-plane weights ----------------
#define PLN 5120
#define HG_SMEM (8*PLN*2)

__global__ __launch_bounds__(256, 2)
void hgemm_kernel(const float* __restrict__ A,
                  const __half* __restrict__ BThi, const __half* __restrict__ BTlo,
                  const float* __restrict__ bias, float* __restrict__ C,
                  const __half* __restrict__ BThi2, const __half* __restrict__ BTlo2,
                  const float* __restrict__ bias2, float* __restrict__ C2,
                  int M, int N, int K,
                  const float* __restrict__ gam, const float* __restrict__ bet,
                  const float* __restrict__ mu,  const float* __restrict__ var,
                  int epi, int dual)
{
    extern __shared__ __half smh[];
    const unsigned smb = (unsigned)__cvta_generic_to_shared(smh);

    const int tid  = threadIdx.x;
    const int warp = tid >> 5;
    const int lane = tid & 31;
    const int gq   = lane >> 2;
    const int tq   = lane & 3;
    int bx = blockIdx.x;
    const int nblk = dual ? (gridDim.x >> 1) : gridDim.x;
    if (dual && bx >= nblk) {
        bx -= nblk;
        BThi = BThi2; BTlo = BTlo2; bias = bias2; C = C2;
    }
    const int cb = bx * 128;
    const int rb = blockIdx.y * 128;

    const int m_w = (warp & 3) * 32;
    const int n_w = (warp >> 2) * 64;

    float acc[2][8][4];
#pragma unroll
    for (int mt = 0; mt < 2; mt++)
#pragma unroll
        for (int nt = 0; nt < 8; nt++)
#pragma unroll
            for (int i = 0; i < 4; i++) acc[mt][nt][i] = 0.f;

    const int lrow = tid >> 1;
    const int seg  = tid & 1;
    const float*  gA  = A    + (size_t)(rb + lrow) * K + seg * 16;
    const __half* gBh = BThi + (size_t)(cb + lrow) * K + seg * 16;
    const __half* gBl = BTlo + (size_t)(cb + lrow) * K + seg * 16;
    const int aoff = lrow * 40 + seg * 16;

    float4 areg[4];

#define LDGA(KC)                                                            \
    {                                                                       \
        _Pragma("unroll")                                                   \
        for (int i = 0; i < 4; i++)                                         \
            areg[i] = *(const float4*)(gA + (KC) + 4*i);                    \
    }

#define CPB(KC, BUF)                                                        \
    {                                                                       \
        const unsigned bh_ = smb + 2u*(4*PLN + (BUF)*PLN + aoff);           \
        const unsigned bl_ = smb + 2u*(6*PLN + (BUF)*PLN + aoff);           \
        cp16(bh_,      gBh + (KC));                                         \
        cp16(bh_ + 16, gBh + (KC) + 8);                                     \
        cp16(bl_,      gBl + (KC));                                         \
        cp16(bl_ + 16, gBl + (KC) + 8);                                     \
        asm volatile("cp.async.commit_group;");                             \
    }

#define STSA(BUF)                                                           \
    {                                                                       \
        uint4 hq, lq;                                                       \
        const unsigned ah_ = smb + 2u*((BUF)*PLN + aoff);                   \
        const unsigned al_ = smb + 2u*(2*PLN + (BUF)*PLN + aoff);           \
        split4(areg[0], hq.x, hq.y, lq.x, lq.y);                            \
        split4(areg[1], hq.z, hq.w, lq.z, lq.w);                            \
        asm volatile("st.shared.v4.b32 [%0], {%1,%2,%3,%4};"                \
            :: "r"(ah_), "r"(hq.x), "r"(hq.y), "r"(hq.z), "r"(hq.w));       \
        asm volatile("st.shared.v4.b32 [%0], {%1,%2,%3,%4};"                \
            :: "r"(al_), "r"(lq.x), "r"(lq.y), "r"(lq.z), "r"(lq.w));       \
        split4(areg[2], hq.x, hq.y, lq.x, lq.y);                            \
        split4(areg[3], hq.z, hq.w, lq.z, lq.w);                            \
        asm volatile("st.shared.v4.b32 [%0], {%1,%2,%3,%4};"                \
            :: "r"(ah_ + 16), "r"(hq.x), "r"(hq.y), "r"(hq.z), "r"(hq.w));  \
        asm volatile("st.shared.v4.b32 [%0], {%1,%2,%3,%4};"                \
            :: "r"(al_ + 16), "r"(lq.x), "r"(lq.y), "r"(lq.z), "r"(lq.w));  \
    }

    LDGA(0);
    CPB(0, 0);
    STSA(0);
    asm volatile("cp.async.wait_group 0;");
    __syncthreads();

    int buf = 0;
    for (int kc = 0; kc < K; kc += 32) {
        const bool last = (kc + 32) >= K;
        if (!last) {
            CPB(kc + 32, buf ^ 1);
            LDGA(kc + 32);
        }

        const int pb = buf * PLN;
#pragma unroll
        for (int k16 = 0; k16 < 32; k16 += 16) {
            unsigned ah[2][4], al[2][4];
#pragma unroll
            for (int mt = 0; mt < 2; mt++) {
                const int r = (m_w + mt*16 + gq) * 40 + k16 + 2*tq;
                ah[mt][0] = *(const unsigned*)&smh[pb + r];
                ah[mt][1] = *(const unsigned*)&smh[pb + r + 320];
                ah[mt][2] = *(const unsigned*)&smh[pb + r + 8];
                ah[mt][3] = *(const unsigned*)&smh[pb + r + 328];
                al[mt][0] = *(const unsigned*)&smh[2*PLN + pb + r];
                al[mt][1] = *(const unsigned*)&smh[2*PLN + pb + r + 320];
                al[mt][2] = *(const unsigned*)&smh[2*PLN + pb + r + 8];
                al[mt][3] = *(const unsigned*)&smh[2*PLN + pb + r + 328];
            }
#pragma unroll
            for (int nt = 0; nt < 8; nt++) {
                const int nb = (n_w + nt*8 + gq) * 40 + k16 + 2*tq;
                unsigned bh[2], bl[2];
                bh[0] = *(const unsigned*)&smh[4*PLN + pb + nb];
                bh[1] = *(const unsigned*)&smh[4*PLN + pb + nb + 8];
                bl[0] = *(const unsigned*)&smh[6*PLN + pb + nb];
                bl[1] = *(const unsigned*)&smh[6*PLN + pb + nb + 8];
#pragma unroll
                for (int mt = 0; mt < 2; mt++) {
                    mma_f16(acc[mt][nt], al[mt], bh);
                    mma_f16(acc[mt][nt], ah[mt], bl);
                    mma_f16(acc[mt][nt], ah[mt], bh);
                }
            }
        }

        if (!last) {
            STSA(buf ^ 1);
            asm volatile("cp.async.wait_group 0;");
            __syncthreads();
            buf ^= 1;
        }
    }

#pragma unroll
    for (int nt = 0; nt < 8; nt++) {
        const int col = cb + n_w + nt*8 + tq*2;
        float s0 = 1.f, s1 = 1.f, t0 = 0.f, t1 = 0.f;
        const float pb0 = bias[col], pb1 = bias[col + 1];
        if (epi == 1) {
            const float i0 = rsqrtf(var[col] + EPSBN);
            const float i1 = rsqrtf(var[col + 1] + EPSBN);
            s0 = gam[col] * i0;     t0 = bet[col]     - mu[col]     * s0;
            s1 = gam[col + 1] * i1; t1 = bet[col + 1] - mu[col + 1] * s1;
        }
#pragma unroll
        for (int mt = 0; mt < 2; mt++) {
            const int r0 = rb + m_w + mt*16 + gq;
#pragma unroll
            for (int half = 0; half < 2; half++) {
                const int r = r0 + half * 8;
                float v0 = acc[mt][nt][half*2 + 0] + pb0;
                float v1 = acc[mt][nt][half*2 + 1] + pb1;
                if (epi == 1) {
                    v0 = gelu_exact(v0 * s0 + t0);
                    v1 = gelu_exact(v1 * s1 + t1);
                }
                *(float2*)&C[(size_t)r * N + col] = make_float2(v0, v1);
            }
        }
    }
#undef LDGA
#undef CPB
#undef STSA
}

// ---------------- fused GATv2 edge kernel (round-5 proven: 122.6 us) ----------------
// grid (HEADS, B), 512 threads, one (sample,head) per block, all data in smem.
#define SM_STRIDE 68
#define GAT_SMEM_FLOATS (2*Nn*SM_STRIDE + 64 + 2*Eg + (Nn+1))
__global__ __launch_bounds__(512)
void gat_kernel(const float* __restrict__ xl, const float* __restrict__ xr,
                const float* __restrict__ att, const float* __restrict__ bo,
                const int* __restrict__ srce, const int* __restrict__ dste,
                const int* __restrict__ off,
                float* __restrict__ out)
{
    extern __shared__ float sm[];
    float*  s_xl   = sm;
    float*  s_xr   = sm + Nn*SM_STRIDE;
    float*  s_att  = sm + 2*Nn*SM_STRIDE;
    float2* s_pair = (float2*)(s_att + 64);
    int*    s_off  = (int*)(s_att + 64 + 2*Eg);

    const int h    = blockIdx.x;
    const int b    = blockIdx.y;
    const int tid  = threadIdx.x;
    const int nthr = 512;

    const float* xlb = xl + (size_t)b * Nn * HID + h * Ch;
    const float* xrb = xr + (size_t)b * Nn * HID + h * Ch;

    for (int i = tid; i < Nn * (Ch/4); i += nthr) {
        int n = i >> 4, c4 = i & 15;
        float4 lv = *(const float4*)(xlb + (size_t)n * HID + 4*c4);
        float4 rv = *(const float4*)(xrb + (size_t)n * HID + 4*c4);
        *(float4*)&s_xl[n*SM_STRIDE + 4*c4] = lv;
        *(float4*)&s_xr[n*SM_STRIDE + 4*c4] = rv;
    }
    if (tid < Ch) s_att[tid] = att[h * Ch + tid];
    if (tid >= nthr - (Nn+1)) s_off[tid - (nthr - (Nn+1))] = off[tid - (nthr - (Nn+1))];
    __syncthreads();

    // ---- phase 1: logits in CSR order (thread per edge) ----
    for (int i = tid; i < Eg; i += nthr) {
        const int s = srce[i];
        const int d = dste[i];
        const float4* pl = (const float4*)&s_xl[s * SM_STRIDE];
        const float4* pr = (const float4*)&s_xr[d * SM_STRIDE];
        float accv = 0.f;
#pragma unroll
        for (int c4 = 0; c4 < 16; c4++) {
            const float4 a4 = *(const float4*)&s_att[4*c4];
            const float4 l4 = pl[c4];
            const float4 r4 = pr[c4];
            float v;
            v = l4.x + r4.x; v = v > 0.f ? v : NEGS * v; accv = fmaf(v, a4.x, accv);
            v = l4.y + r4.y; v = v > 0.f ? v : NEGS * v; accv = fmaf(v, a4.y, accv);
            v = l4.z + r4.z; v = v > 0.f ? v : NEGS * v; accv = fmaf(v, a4.z, accv);
            v = l4.w + r4.w; v = v > 0.f ? v : NEGS * v; accv = fmaf(v, a4.w, accv);
        }
        s_pair[i] = make_float2(accv, __int_as_float(s * SM_STRIDE));
    }
    __syncthreads();

    // ---- phase 2: warp per node; half-warp per edge, float4 channels ----
    const int warp = tid >> 5, lane = tid & 31;
    const int cg = lane & 15;
    const int ep = lane >> 4;
    const float4 bo4 = *(const float4*)(bo + h*Ch + 4*cg);

    for (int n = warp; n < Nn; n += 16) {
        const int o0  = s_off[n];
        const int deg = s_off[n+1] - o0;

        float m = -INFINITY;
        for (int i = lane; i < deg; i += 32) m = fmaxf(m, s_pair[o0 + i].x);
#pragma unroll
        for (int d = 16; d; d >>= 1) m = fmaxf(m, __shfl_xor_sync(0xffffffffu, m, d));

        float ssum = 0.f;
        for (int i = lane; i < deg; i += 32) ssum += expf(s_pair[o0 + i].x - m);
#pragma unroll
        for (int d = 16; d; d >>= 1) ssum += __shfl_xor_sync(0xffffffffu, ssum, d);
        const float inv = 1.0f / (ssum + 1e-16f);

        for (int i = lane; i < deg; i += 32)
            s_pair[o0 + i].x = expf(s_pair[o0 + i].x - m) * inv;
        __syncwarp();

        float4 acc = make_float4(0.f, 0.f, 0.f, 0.f);
#pragma unroll 4
        for (int j = ep; j < deg; j += 2) {
            const float2 p = s_pair[o0 + j];
            const int soff = __float_as_int(p.y);
            const float4 xv = *(const float4*)&s_xl[soff + 4*cg];
            acc.x = fmaf(p.x, xv.x, acc.x);
            acc.y = fmaf(p.x, xv.y, acc.y);
            acc.z = fmaf(p.x, xv.z, acc.z);
            acc.w = fmaf(p.x, xv.w, acc.w);
        }
        acc.x += __shfl_down_sync(0xffffffffu, acc.x, 16);
        acc.y += __shfl_down_sync(0xffffffffu, acc.y, 16);
        acc.z += __shfl_down_sync(0xffffffffu, acc.z, 16);
        acc.w += __shfl_down_sync(0xffffffffu, acc.w, 16);

        if (ep == 0) {
            float4 r;
            r.x = gelu_exact(acc.x + bo4.x);
            r.y = gelu_exact(acc.y + bo4.y);
            r.z = gelu_exact(acc.z + bo4.z);
            r.w = gelu_exact(acc.w + bo4.w);
            *(float4*)(out + (size_t)(b*Nn + n) * HID + h*Ch + 4*cg) = r;
        }
    }
}

// ---------------- fused mean-pool + output proj + BN + gelu ----------------
__global__ __launch_bounds__(256)
void tail_kernel(const float* __restrict__ hin, const float* __restrict__ W2,
                 const float* __restrict__ b2,
                 const float* __restrict__ g2, const float* __restrict__ be2,
                 const float* __restrict__ m2, const float* __restrict__ v2,
                 float* __restrict__ out) {
    const int b = blockIdx.x, c = threadIdx.x;
    __shared__ float sp[HID];
    float s = 0.f;
    const float* base = hin + (size_t)b * Nn * HID + c;
    for (int n = 0; n < Nn; n++) s += base[(size_t)n * HID];
    sp[c] = s * (1.0f / Nn);
    __syncthreads();
    float acc = 0.f;
    for (int k = 0; k < HID; k++) acc = fmaf(sp[k], W2[(size_t)k * HID + c], acc);
    acc += b2[c];
    float inv = rsqrtf(v2[c] + EPSBN);
    acc = (acc - m2[c]) * inv * g2[c] + be2[c];
    out[b * HID + c] = gelu_exact(acc);
}

// ---------------- launch ----------------
extern "C" void kernel_launch(void* const* d_in, const int* in_sizes, int n_in,
                              void* d_out, int out_size) {
    const float* x    = (const float*)d_in[0];
    const int*   ei   = (const int*)  d_in[1];
    const float* W1   = (const float*)d_in[2];
    const float* b1   = (const float*)d_in[3];
    const float* g1   = (const float*)d_in[4];
    const float* be1  = (const float*)d_in[5];
    const float* m1   = (const float*)d_in[6];
    const float* v1   = (const float*)d_in[7];
    const float* Wl0  = (const float*)d_in[8];
    const float* bl0  = (const float*)d_in[9];
    const float* Wr0  = (const float*)d_in[10];
    const float* br0  = (const float*)d_in[11];
    const float* att0 = (const float*)d_in[12];
    const float* bo0  = (const float*)d_in[13];
    const float* Wl1  = (const float*)d_in[14];
    const float* bl1  = (const float*)d_in[15];
    const float* Wr1  = (const float*)d_in[16];
    const float* br1  = (const float*)d_in[17];
    const float* att1 = (const float*)d_in[18];
    const float* bo1  = (const float*)d_in[19];
    const float* W2   = (const float*)d_in[20];
    const float* b2   = (const float*)d_in[21];
    const float* g2   = (const float*)d_in[22];
    const float* be2  = (const float*)d_in[23];
    const float* m2   = (const float*)d_in[24];
    const float* v2   = (const float*)d_in[25];

    float *h, *h2, *xl, *xr;
    int *off, *srce, *dste;
    __half *wthi, *wtlo;
    cudaGetSymbolAddress((void**)&h,    g_h);
    cudaGetSymbolAddress((void**)&h2,   g_h2);
    cudaGetSymbolAddress((void**)&xl,   g_xl);
    cudaGetSymbolAddress((void**)&xr,   g_xr);
    cudaGetSymbolAddress((void**)&off,  g_off);
    cudaGetSymbolAddress((void**)&srce, g_srce);
    cudaGetSymbolAddress((void**)&dste, g_dste);
    cudaGetSymbolAddress((void**)&wthi, g_wthi);
    cudaGetSymbolAddress((void**)&wtlo, g_wtlo);

    const int gat_smem = GAT_SMEM_FLOATS * (int)sizeof(float);   // ~206 KB
    cudaFuncSetAttribute(gat_kernel, cudaFuncAttributeMaxDynamicSharedMemorySize, gat_smem);
    cudaFuncSetAttribute(hgemm_kernel, cudaFuncAttributeMaxDynamicSharedMemorySize, HG_SMEM);

    build_csr_kernel<<<1, 256>>>(ei, off, srce, dste);
    convT_all_kernel<<<(WT_TOT + 255)/256, 256>>>(W1, Wl0, Wr0, Wl1, Wr1, wthi, wtlo);

    // node_proj: h = gelu(BN(x @ W1 + b1))
    hgemm_kernel<<<dim3(HID/128, ROWS/128), 256, HG_SMEM>>>(
        x, wthi + WT_W1, wtlo + WT_W1, b1, h,
        0, 0, 0, 0, ROWS, HID, F_IN, g1, be1, m1, v1, 1, 0);

    // layer 0
    hgemm_kernel<<<dim3(2*HID/128, ROWS/128), 256, HG_SMEM>>>(
        h, wthi + WT_L0, wtlo + WT_L0, bl0, xl,
        wthi + WT_R0, wtlo + WT_R0, br0, xr, ROWS, HID, HID, 0, 0, 0, 0, 0, 1);
    gat_kernel<<<dim3(HEADS, Bsz), 512, gat_smem>>>(xl, xr, att0, bo0, srce, dste, off, h2);

    // layer 1
    hgemm_kernel<<<dim3(2*HID/128, ROWS/128), 256, HG_SMEM>>>(
        h2, wthi + WT_L1, wtlo + WT_L1, bl1, xl,
        wthi + WT_R1, wtlo + WT_R1, br1, xr, ROWS, HID, HID, 0, 0, 0, 0, 0, 1);
    gat_kernel<<<dim3(HEADS, Bsz), 512, gat_smem>>>(xl, xr, att1, bo1, srce, dste, off, h);

    tail_kernel<<<Bsz, 256>>>(h, W2, b2, g2, be2, m2, v2, (float*)d_out);
}

// round 14
// speedup vs baseline: 1.5538x; 1.5538x over previous
#include <cuda_runtime.h>
#include <cuda_fp16.h>
#include <math.h>

// ---------------- problem constants ----------------
#define Bsz   64
#define Nn    256
#define CT    3
#define HID   256
#define HEADS 4
#define Ch    64
#define Eg    8192
#define F_IN  (Nn*CT)
#define ROWS  (Bsz*Nn)
#define NEGS  0.2f
#define EPSBN 1e-5f

// ---------------- scratch ----------------
__device__ float  g_h [ROWS*HID];
__device__ float  g_h2[ROWS*HID];
__device__ float  g_xl[ROWS*HID];
__device__ float  g_xr[ROWS*HID];
__device__ int    g_off[Nn+1];
__device__ int    g_srce[Eg];
__device__ int    g_dste[Eg];
#define WT_W1  0
#define WT_L0  (F_IN*HID)
#define WT_R0  (F_IN*HID + HID*HID)
#define WT_L1  (F_IN*HID + 2*HID*HID)
#define WT_R1  (F_IN*HID + 3*HID*HID)
#define WT_TOT (F_IN*HID + 4*HID*HID)
__device__ __half g_wthi[WT_TOT];
__device__ __half g_wtlo[WT_TOT];

__device__ __forceinline__ float gelu_exact(float x) { return x * normcdff(x); }

__device__ __forceinline__ void mma_f16(float* c, const unsigned* a, const unsigned* b) {
    asm("mma.sync.aligned.m16n8k16.row.col.f32.f16.f16.f32 "
        "{%0,%1,%2,%3},{%4,%5,%6,%7},{%8,%9},{%0,%1,%2,%3};"
        : "+f"(c[0]), "+f"(c[1]), "+f"(c[2]), "+f"(c[3])
        : "r"(a[0]), "r"(a[1]), "r"(a[2]), "r"(a[3]), "r"(b[0]), "r"(b[1]));
}

__device__ __forceinline__ void cp16(unsigned saddr, const void* g) {
    asm volatile("cp.async.cg.shared.global [%0], [%1], 16;" :: "r"(saddr), "l"(g));
}

__device__ __forceinline__ void split4(float4 f, unsigned& h0, unsigned& h1,
                                       unsigned& l0, unsigned& l1) {
    __half2 a = __float22half2_rn(make_float2(f.x, f.y));
    __half2 b = __float22half2_rn(make_float2(f.z, f.w));
    float2 fa = __half22float2(a);
    float2 fb = __half22float2(b);
    __half2 c = __float22half2_rn(make_float2(f.x - fa.x, f.y - fa.y));
    __half2 d = __float22half2_rn(make_float2(f.z - fb.x, f.w - fb.y));
    h0 = *(unsigned*)&a; h1 = *(unsigned*)&b;
    l0 = *(unsigned*)&c; l1 = *(unsigned*)&d;
}

// ---------------- deterministic CSR build (srce + dste) ----------------
__global__ __launch_bounds__(256)
void build_csr_kernel(const int* __restrict__ ei,
                      int* __restrict__ off,
                      int* __restrict__ srce, int* __restrict__ dste) {
    __shared__ int hist[8][Nn];
    __shared__ int s_loc[Eg];
    __shared__ int s_off[Nn+1];

    const int tid  = threadIdx.x;
    const int w    = tid >> 5;
    const int lane = tid & 31;
    const int* srcA = ei;
    const int* dstA = ei + Eg;

    for (int i = tid; i < 8 * Nn; i += 256) ((int*)hist)[i] = 0;
    __syncthreads();

    const int base = w * 1024;
#pragma unroll 1
    for (int g = 0; g < 32; g++) {
        const int e = base + g * 32 + lane;
        const int d = dstA[e];
        unsigned mask = __match_any_sync(0xffffffffu, d);
        int leader = __ffs(mask) - 1;
        int rank   = __popc(mask & ((1u << lane) - 1u));
        int cur    = hist[w][d];
        s_loc[e]   = cur + rank;
        __syncwarp();
        if (lane == leader) hist[w][d] = cur + __popc(mask);
        __syncwarp();
    }
    __syncthreads();

    __shared__ int tot[Nn];
    if (tid < Nn) {
        int run = 0;
#pragma unroll
        for (int ww = 0; ww < 8; ww++) {
            int c = hist[ww][tid];
            hist[ww][tid] = run;
            run += c;
        }
        tot[tid] = run;
    }
    __syncthreads();
    if (tid == 0) {
        int run = 0;
        for (int n = 0; n < Nn; n++) { s_off[n] = run; run += tot[n]; }
        s_off[Nn] = run;
    }
    __syncthreads();

    if (tid < Nn) off[tid] = s_off[tid];
    if (tid == 0) off[Nn] = s_off[Nn];

    for (int e = tid; e < Eg; e += 256) {
        const int d  = dstA[e];
        const int we = e >> 10;
        const int pos = s_off[d] + hist[we][d] + s_loc[e];
        srce[pos] = srcA[e];
        dste[pos] = d;
    }
}

// ---------------- fused weight transpose+split ----------------
__global__ __launch_bounds__(256)
void convT_all_kernel(const float* __restrict__ W1,
                      const float* __restrict__ Wl0, const float* __restrict__ Wr0,
                      const float* __restrict__ Wl1, const float* __restrict__ Wr1,
                      __half* __restrict__ Thi, __half* __restrict__ Tlo) {
    int idx = blockIdx.x * 256 + threadIdx.x;
    if (idx >= WT_TOT) return;
    const float* W; int Kd, loc;
    if (idx < WT_L0)      { W = W1;  Kd = F_IN; loc = idx - WT_W1; }
    else if (idx < WT_R0) { W = Wl0; Kd = HID;  loc = idx - WT_L0; }
    else if (idx < WT_L1) { W = Wr0; Kd = HID;  loc = idx - WT_R0; }
    else if (idx < WT_R1) { W = Wl1; Kd = HID;  loc = idx - WT_L1; }
    else                  { W = Wr1; Kd = HID;  loc = idx - WT_R1; }
    int n = loc / Kd, k = loc % Kd;
    float f = W[(size_t)k * HID + n];
    __half h = __float2half_rn(f);
    Thi[idx] = h;
    Tlo[idx] = __float2half_rn(f - __half2float(h));
}

// ---------------- GEMM (round-9 proven): fp32 A loader-split, fp16-plane weights ----------------
#define PLN 5120
#define HG_SMEM (8*PLN*2)

__global__ __launch_bounds__(256, 2)
void hgemm_kernel(const float* __restrict__ A,
                  const __half* __restrict__ BThi, const __half* __restrict__ BTlo,
                  const float* __restrict__ bias, float* __restrict__ C,
                  const __half* __restrict__ BThi2, const __half* __restrict__ BTlo2,
                  const float* __restrict__ bias2, float* __restrict__ C2,
                  int M, int N, int K,
                  const float* __restrict__ gam, const float* __restrict__ bet,
                  const float* __restrict__ mu,  const float* __restrict__ var,
                  int epi, int dual)
{
    extern __shared__ __half smh[];
    const unsigned smb = (unsigned)__cvta_generic_to_shared(smh);

    const int tid  = threadIdx.x;
    const int warp = tid >> 5;
    const int lane = tid & 31;
    const int gq   = lane >> 2;
    const int tq   = lane & 3;
    int bx = blockIdx.x;
    const int nblk = dual ? (gridDim.x >> 1) : gridDim.x;
    if (dual && bx >= nblk) {
        bx -= nblk;
        BThi = BThi2; BTlo = BTlo2; bias = bias2; C = C2;
    }
    const int cb = bx * 128;
    const int rb = blockIdx.y * 128;

    const int m_w = (warp & 3) * 32;
    const int n_w = (warp >> 2) * 64;

    float acc[2][8][4];
#pragma unroll
    for (int mt = 0; mt < 2; mt++)
#pragma unroll
        for (int nt = 0; nt < 8; nt++)
#pragma unroll
            for (int i = 0; i < 4; i++) acc[mt][nt][i] = 0.f;

    const int lrow = tid >> 1;
    const int seg  = tid & 1;
    const float*  gA  = A    + (size_t)(rb + lrow) * K + seg * 16;
    const __half* gBh = BThi + (size_t)(cb + lrow) * K + seg * 16;
    const __half* gBl = BTlo + (size_t)(cb + lrow) * K + seg * 16;
    const int aoff = lrow * 40 + seg * 16;

    float4 areg[4];

#define LDGA(KC)                                                            \
    {                                                                       \
        _Pragma("unroll")                                                   \
        for (int i = 0; i < 4; i++)                                         \
            areg[i] = *(const float4*)(gA + (KC) + 4*i);                    \
    }

#define CPB(KC, BUF)                                                        \
    {                                                                       \
        const unsigned bh_ = smb + 2u*(4*PLN + (BUF)*PLN + aoff);           \
        const unsigned bl_ = smb + 2u*(6*PLN + (BUF)*PLN + aoff);           \
        cp16(bh_,      gBh + (KC));                                         \
        cp16(bh_ + 16, gBh + (KC) + 8);                                     \
        cp16(bl_,      gBl + (KC));                                         \
        cp16(bl_ + 16, gBl + (KC) + 8);                                     \
        asm volatile("cp.async.commit_group;");                             \
    }

#define STSA(BUF)                                                           \
    {                                                                       \
        uint4 hq, lq;                                                       \
        const unsigned ah_ = smb + 2u*((BUF)*PLN + aoff);                   \
        const unsigned al_ = smb + 2u*(2*PLN + (BUF)*PLN + aoff);           \
        split4(areg[0], hq.x, hq.y, lq.x, lq.y);                            \
        split4(areg[1], hq.z, hq.w, lq.z, lq.w);                            \
        asm volatile("st.shared.v4.b32 [%0], {%1,%2,%3,%4};"                \
            :: "r"(ah_), "r"(hq.x), "r"(hq.y), "r"(hq.z), "r"(hq.w));       \
        asm volatile("st.shared.v4.b32 [%0], {%1,%2,%3,%4};"                \
            :: "r"(al_), "r"(lq.x), "r"(lq.y), "r"(lq.z), "r"(lq.w));       \
        split4(areg[2], hq.x, hq.y, lq.x, lq.y);                            \
        split4(areg[3], hq.z, hq.w, lq.z, lq.w);                            \
        asm volatile("st.shared.v4.b32 [%0], {%1,%2,%3,%4};"                \
            :: "r"(ah_ + 16), "r"(hq.x), "r"(hq.y), "r"(hq.z), "r"(hq.w));  \
        asm volatile("st.shared.v4.b32 [%0], {%1,%2,%3,%4};"                \
            :: "r"(al_ + 16), "r"(lq.x), "r"(lq.y), "r"(lq.z), "r"(lq.w));  \
    }

    LDGA(0);
    CPB(0, 0);
    STSA(0);
    asm volatile("cp.async.wait_group 0;");
    __syncthreads();

    int buf = 0;
    for (int kc = 0; kc < K; kc += 32) {
        const bool last = (kc + 32) >= K;
        if (!last) {
            CPB(kc + 32, buf ^ 1);
            LDGA(kc + 32);
        }

        const int pb = buf * PLN;
#pragma unroll
        for (int k16 = 0; k16 < 32; k16 += 16) {
            unsigned ah[2][4], al[2][4];
#pragma unroll
            for (int mt = 0; mt < 2; mt++) {
                const int r = (m_w + mt*16 + gq) * 40 + k16 + 2*tq;
                ah[mt][0] = *(const unsigned*)&smh[pb + r];
                ah[mt][1] = *(const unsigned*)&smh[pb + r + 320];
                ah[mt][2] = *(const unsigned*)&smh[pb + r + 8];
                ah[mt][3] = *(const unsigned*)&smh[pb + r + 328];
                al[mt][0] = *(const unsigned*)&smh[2*PLN + pb + r];
                al[mt][1] = *(const unsigned*)&smh[2*PLN + pb + r + 320];
                al[mt][2] = *(const unsigned*)&smh[2*PLN + pb + r + 8];
                al[mt][3] = *(const unsigned*)&smh[2*PLN + pb + r + 328];
            }
#pragma unroll
            for (int nt = 0; nt < 8; nt++) {
                const int nb = (n_w + nt*8 + gq) * 40 + k16 + 2*tq;
                unsigned bh[2], bl[2];
                bh[0] = *(const unsigned*)&smh[4*PLN + pb + nb];
                bh[1] = *(const unsigned*)&smh[4*PLN + pb + nb + 8];
                bl[0] = *(const unsigned*)&smh[6*PLN + pb + nb];
                bl[1] = *(const unsigned*)&smh[6*PLN + pb + nb + 8];
#pragma unroll
                for (int mt = 0; mt < 2; mt++) {
                    mma_f16(acc[mt][nt], al[mt], bh);
                    mma_f16(acc[mt][nt], ah[mt], bl);
                    mma_f16(acc[mt][nt], ah[mt], bh);
                }
            }
        }

        if (!last) {
            STSA(buf ^ 1);
            asm volatile("cp.async.wait_group 0;");
            __syncthreads();
            buf ^= 1;
        }
    }

#pragma unroll
    for (int nt = 0; nt < 8; nt++) {
        const int col = cb + n_w + nt*8 + tq*2;
        float s0 = 1.f, s1 = 1.f, t0 = 0.f, t1 = 0.f;
        const float pb0 = bias[col], pb1 = bias[col + 1];
        if (epi == 1) {
            const float i0 = rsqrtf(var[col] + EPSBN);
            const float i1 = rsqrtf(var[col + 1] + EPSBN);
            s0 = gam[col] * i0;     t0 = bet[col]     - mu[col]     * s0;
            s1 = gam[col + 1] * i1; t1 = bet[col + 1] - mu[col + 1] * s1;
        }
#pragma unroll
        for (int mt = 0; mt < 2; mt++) {
            const int r0 = rb + m_w + mt*16 + gq;
#pragma unroll
            for (int half = 0; half < 2; half++) {
                const int r = r0 + half * 8;
                float v0 = acc[mt][nt][half*2 + 0] + pb0;
                float v1 = acc[mt][nt][half*2 + 1] + pb1;
                if (epi == 1) {
                    v0 = gelu_exact(v0 * s0 + t0);
                    v1 = gelu_exact(v1 * s1 + t1);
                }
                *(float2*)&C[(size_t)r * N + col] = make_float2(v0, v1);
            }
        }
    }
#undef LDGA
#undef CPB
#undef STSA
}

// ---------------- fused GATv2 edge kernel (round-5 proven: 122.6 us) ----------------
// grid (HEADS, B), 512 threads, one (sample,head) per block, all data in smem.
#define SM_STRIDE 68
#define GAT_SMEM_FLOATS (2*Nn*SM_STRIDE + 64 + 2*Eg + (Nn+1))
__global__ __launch_bounds__(512)
void gat_kernel(const float* __restrict__ xl, const float* __restrict__ xr,
                const float* __restrict__ att, const float* __restrict__ bo,
                const int* __restrict__ srce, const int* __restrict__ dste,
                const int* __restrict__ off,
                float* __restrict__ out)
{
    extern __shared__ float sm[];
    float*  s_xl   = sm;
    float*  s_xr   = sm + Nn*SM_STRIDE;
    float*  s_att  = sm + 2*Nn*SM_STRIDE;
    float2* s_pair = (float2*)(s_att + 64);
    int*    s_off  = (int*)(s_att + 64 + 2*Eg);

    const int h    = blockIdx.x;
    const int b    = blockIdx.y;
    const int tid  = threadIdx.x;
    const int nthr = 512;

    const float* xlb = xl + (size_t)b * Nn * HID + h * Ch;
    const float* xrb = xr + (size_t)b * Nn * HID + h * Ch;

    for (int i = tid; i < Nn * (Ch/4); i += nthr) {
        int n = i >> 4, c4 = i & 15;
        float4 lv = *(const float4*)(xlb + (size_t)n * HID + 4*c4);
        float4 rv = *(const float4*)(xrb + (size_t)n * HID + 4*c4);
        *(float4*)&s_xl[n*SM_STRIDE + 4*c4] = lv;
        *(float4*)&s_xr[n*SM_STRIDE + 4*c4] = rv;
    }
    if (tid < Ch) s_att[tid] = att[h * Ch + tid];
    if (tid >= nthr - (Nn+1)) s_off[tid - (nthr - (Nn+1))] = off[tid - (nthr - (Nn+1))];
    __syncthreads();

    // ---- phase 1: logits in CSR order (thread per edge) ----
    for (int i = tid; i < Eg; i += nthr) {
        const int s = srce[i];
        const int d = dste[i];
        const float4* pl = (const float4*)&s_xl[s * SM_STRIDE];
        const float4* pr = (const float4*)&s_xr[d * SM_STRIDE];
        float accv = 0.f;
#pragma unroll
        for (int c4 = 0; c4 < 16; c4++) {
            const float4 a4 = *(const float4*)&s_att[4*c4];
            const float4 l4 = pl[c4];
            const float4 r4 = pr[c4];
            float v;
            v = l4.x + r4.x; v = v > 0.f ? v : NEGS * v; accv = fmaf(v, a4.x, accv);
            v = l4.y + r4.y; v = v > 0.f ? v : NEGS * v; accv = fmaf(v, a4.y, accv);
            v = l4.z + r4.z; v = v > 0.f ? v : NEGS * v; accv = fmaf(v, a4.z, accv);
            v = l4.w + r4.w; v = v > 0.f ? v : NEGS * v; accv = fmaf(v, a4.w, accv);
        }
        s_pair[i] = make_float2(accv, __int_as_float(s * SM_STRIDE));
    }
    __syncthreads();

    // ---- phase 2: warp per node; half-warp per edge, float4 channels ----
    const int warp = tid >> 5, lane = tid & 31;
    const int cg = lane & 15;
    const int ep = lane >> 4;
    const float4 bo4 = *(const float4*)(bo + h*Ch + 4*cg);

    for (int n = warp; n < Nn; n += 16) {
        const int o0  = s_off[n];
        const int deg = s_off[n+1] - o0;

        float m = -INFINITY;
        for (int i = lane; i < deg; i += 32) m = fmaxf(m, s_pair[o0 + i].x);
#pragma unroll
        for (int d = 16; d; d >>= 1) m = fmaxf(m, __shfl_xor_sync(0xffffffffu, m, d));

        float ssum = 0.f;
        for (int i = lane; i < deg; i += 32) ssum += expf(s_pair[o0 + i].x - m);
#pragma unroll
        for (int d = 16; d; d >>= 1) ssum += __shfl_xor_sync(0xffffffffu, ssum, d);
        const float inv = 1.0f / (ssum + 1e-16f);

        for (int i = lane; i < deg; i += 32)
            s_pair[o0 + i].x = expf(s_pair[o0 + i].x - m) * inv;
        __syncwarp();

        float4 acc = make_float4(0.f, 0.f, 0.f, 0.f);
#pragma unroll 4
        for (int j = ep; j < deg; j += 2) {
            const float2 p = s_pair[o0 + j];
            const int soff = __float_as_int(p.y);
            const float4 xv = *(const float4*)&s_xl[soff + 4*cg];
            acc.x = fmaf(p.x, xv.x, acc.x);
            acc.y = fmaf(p.x, xv.y, acc.y);
            acc.z = fmaf(p.x, xv.z, acc.z);
            acc.w = fmaf(p.x, xv.w, acc.w);
        }
        acc.x += __shfl_down_sync(0xffffffffu, acc.x, 16);
        acc.y += __shfl_down_sync(0xffffffffu, acc.y, 16);
        acc.z += __shfl_down_sync(0xffffffffu, acc.z, 16);
        acc.w += __shfl_down_sync(0xffffffffu, acc.w, 16);

        if (ep == 0) {
            float4 r;
            r.x = gelu_exact(acc.x + bo4.x);
            r.y = gelu_exact(acc.y + bo4.y);
            r.z = gelu_exact(acc.z + bo4.z);
            r.w = gelu_exact(acc.w + bo4.w);
            *(float4*)(out + (size_t)(b*Nn + n) * HID + h*Ch + 4*cg) = r;
        }
    }
}

// ---------------- fused mean-pool + output proj + BN + gelu ----------------
__global__ __launch_bounds__(256)
void tail_kernel(const float* __restrict__ hin, const float* __restrict__ W2,
                 const float* __restrict__ b2,
                 const float* __restrict__ g2, const float* __restrict__ be2,
                 const float* __restrict__ m2, const float* __restrict__ v2,
                 float* __restrict__ out) {
    const int b = blockIdx.x, c = threadIdx.x;
    __shared__ float sp[HID];
    float s = 0.f;
    const float* base = hin + (size_t)b * Nn * HID + c;
    for (int n = 0; n < Nn; n++) s += base[(size_t)n * HID];
    sp[c] = s * (1.0f / Nn);
    __syncthreads();
    float acc = 0.f;
    for (int k = 0; k < HID; k++) acc = fmaf(sp[k], W2[(size_t)k * HID + c], acc);
    acc += b2[c];
    float inv = rsqrtf(v2[c] + EPSBN);
    acc = (acc - m2[c]) * inv * g2[c] + be2[c];
    out[b * HID + c] = gelu_exact(acc);
}

// ---------------- launch ----------------
extern "C" void kernel_launch(void* const* d_in, const int* in_sizes, int n_in,
                              void* d_out, int out_size) {
    const float* x    = (const float*)d_in[0];
    const int*   ei   = (const int*)  d_in[1];
    const float* W1   = (const float*)d_in[2];
    const float* b1   = (const float*)d_in[3];
    const float* g1   = (const float*)d_in[4];
    const float* be1  = (const float*)d_in[5];
    const float* m1   = (const float*)d_in[6];
    const float* v1   = (const float*)d_in[7];
    const float* Wl0  = (const float*)d_in[8];
    const float* bl0  = (const float*)d_in[9];
    const float* Wr0  = (const float*)d_in[10];
    const float* br0  = (const float*)d_in[11];
    const float* att0 = (const float*)d_in[12];
    const float* bo0  = (const float*)d_in[13];
    const float* Wl1  = (const float*)d_in[14];
    const float* bl1  = (const float*)d_in[15];
    const float* Wr1  = (const float*)d_in[16];
    const float* br1  = (const float*)d_in[17];
    const float* att1 = (const float*)d_in[18];
    const float* bo1  = (const float*)d_in[19];
    const float* W2   = (const float*)d_in[20];
    const float* b2   = (const float*)d_in[21];
    const float* g2   = (const float*)d_in[22];
    const float* be2  = (const float*)d_in[23];
    const float* m2   = (const float*)d_in[24];
    const float* v2   = (const float*)d_in[25];

    float *h, *h2, *xl, *xr;
    int *off, *srce, *dste;
    __half *wthi, *wtlo;
    cudaGetSymbolAddress((void**)&h,    g_h);
    cudaGetSymbolAddress((void**)&h2,   g_h2);
    cudaGetSymbolAddress((void**)&xl,   g_xl);
    cudaGetSymbolAddress((void**)&xr,   g_xr);
    cudaGetSymbolAddress((void**)&off,  g_off);
    cudaGetSymbolAddress((void**)&srce, g_srce);
    cudaGetSymbolAddress((void**)&dste, g_dste);
    cudaGetSymbolAddress((void**)&wthi, g_wthi);
    cudaGetSymbolAddress((void**)&wtlo, g_wtlo);

    const int gat_smem = GAT_SMEM_FLOATS * (int)sizeof(float);   // ~206 KB
    cudaFuncSetAttribute(gat_kernel, cudaFuncAttributeMaxDynamicSharedMemorySize, gat_smem);
    cudaFuncSetAttribute(hgemm_kernel, cudaFuncAttributeMaxDynamicSharedMemorySize, HG_SMEM);

    build_csr_kernel<<<1, 256>>>(ei, off, srce, dste);
    convT_all_kernel<<<(WT_TOT + 255)/256, 256>>>(W1, Wl0, Wr0, Wl1, Wr1, wthi, wtlo);

    // node_proj: h = gelu(BN(x @ W1 + b1))
    hgemm_kernel<<<dim3(HID/128, ROWS/128), 256, HG_SMEM>>>(
        x, wthi + WT_W1, wtlo + WT_W1, b1, h,
        0, 0, 0, 0, ROWS, HID, F_IN, g1, be1, m1, v1, 1, 0);

    // layer 0
    hgemm_kernel<<<dim3(2*HID/128, ROWS/128), 256, HG_SMEM>>>(
        h, wthi + WT_L0, wtlo + WT_L0, bl0, xl,
        wthi + WT_R0, wtlo + WT_R0, br0, xr, ROWS, HID, HID, 0, 0, 0, 0, 0, 1);
    gat_kernel<<<dim3(HEADS, Bsz), 512, gat_smem>>>(xl, xr, att0, bo0, srce, dste, off, h2);

    // layer 1
    hgemm_kernel<<<dim3(2*HID/128, ROWS/128), 256, HG_SMEM>>>(
        h2, wthi + WT_L1, wtlo + WT_L1, bl1, xl,
        wthi + WT_R1, wtlo + WT_R1, br1, xr, ROWS, HID, HID, 0, 0, 0, 0, 0, 1);
    gat_kernel<<<dim3(HEADS, Bsz), 512, gat_smem>>>(xl, xr, att1, bo1, srce, dste, off, h);

    tail_kernel<<<Bsz, 256>>>(h, W2, b2, g2, be2, m2, v2, (float*)d_out);
}

// round 15
// speedup vs baseline: 1.5613x; 1.0048x over previous
#include <cuda_runtime.h>
#include <cuda_fp16.h>
#include <math.h>

// ---------------- problem constants ----------------
#define Bsz   64
#define Nn    256
#define CT    3
#define HID   256
#define HEADS 4
#define Ch    64
#define Eg    8192
#define F_IN  (Nn*CT)
#define ROWS  (Bsz*Nn)
#define NEGS  0.2f
#define EPSBN 1e-5f

// ---------------- scratch ----------------
__device__ float  g_h [ROWS*HID];
__device__ float  g_h2[ROWS*HID];
__device__ float  g_xl[ROWS*HID];
__device__ float  g_xr[ROWS*HID];
__device__ int    g_off[Nn+1];
__device__ int    g_srce[Eg];
__device__ int    g_dste[Eg];
#define WT_W1  0
#define WT_L0  (F_IN*HID)
#define WT_R0  (F_IN*HID + HID*HID)
#define WT_L1  (F_IN*HID + 2*HID*HID)
#define WT_R1  (F_IN*HID + 3*HID*HID)
#define WT_TOT (F_IN*HID + 4*HID*HID)
__device__ __half g_wthi[WT_TOT];
__device__ __half g_wtlo[WT_TOT];

__device__ __forceinline__ float gelu_exact(float x) { return x * normcdff(x); }

__device__ __forceinline__ void mma_f16(float* c, const unsigned* a, const unsigned* b) {
    asm("mma.sync.aligned.m16n8k16.row.col.f32.f16.f16.f32 "
        "{%0,%1,%2,%3},{%4,%5,%6,%7},{%8,%9},{%0,%1,%2,%3};"
        : "+f"(c[0]), "+f"(c[1]), "+f"(c[2]), "+f"(c[3])
        : "r"(a[0]), "r"(a[1]), "r"(a[2]), "r"(a[3]), "r"(b[0]), "r"(b[1]));
}

__device__ __forceinline__ void cp16(unsigned saddr, const void* g) {
    asm volatile("cp.async.cg.shared.global [%0], [%1], 16;" :: "r"(saddr), "l"(g));
}

__device__ __forceinline__ void split4(float4 f, unsigned& h0, unsigned& h1,
                                       unsigned& l0, unsigned& l1) {
    __half2 a = __float22half2_rn(make_float2(f.x, f.y));
    __half2 b = __float22half2_rn(make_float2(f.z, f.w));
    float2 fa = __half22float2(a);
    float2 fb = __half22float2(b);
    __half2 c = __float22half2_rn(make_float2(f.x - fa.x, f.y - fa.y));
    __half2 d = __float22half2_rn(make_float2(f.z - fb.x, f.w - fb.y));
    h0 = *(unsigned*)&a; h1 = *(unsigned*)&b;
    l0 = *(unsigned*)&c; l1 = *(unsigned*)&d;
}

// ---------------- deterministic CSR build (srce + dste) ----------------
__global__ __launch_bounds__(256)
void build_csr_kernel(const int* __restrict__ ei,
                      int* __restrict__ off,
                      int* __restrict__ srce, int* __restrict__ dste) {
    __shared__ int hist[8][Nn];
    __shared__ int s_loc[Eg];
    __shared__ int s_off[Nn+1];

    const int tid  = threadIdx.x;
    const int w    = tid >> 5;
    const int lane = tid & 31;
    const int* srcA = ei;
    const int* dstA = ei + Eg;

    for (int i = tid; i < 8 * Nn; i += 256) ((int*)hist)[i] = 0;
    __syncthreads();

    const int base = w * 1024;
#pragma unroll 1
    for (int g = 0; g < 32; g++) {
        const int e = base + g * 32 + lane;
        const int d = dstA[e];
        unsigned mask = __match_any_sync(0xffffffffu, d);
        int leader = __ffs(mask) - 1;
        int rank   = __popc(mask & ((1u << lane) - 1u));
        int cur    = hist[w][d];
        s_loc[e]   = cur + rank;
        __syncwarp();
        if (lane == leader) hist[w][d] = cur + __popc(mask);
        __syncwarp();
    }
    __syncthreads();

    __shared__ int tot[Nn];
    if (tid < Nn) {
        int run = 0;
#pragma unroll
        for (int ww = 0; ww < 8; ww++) {
            int c = hist[ww][tid];
            hist[ww][tid] = run;
            run += c;
        }
        tot[tid] = run;
    }
    __syncthreads();
    if (tid == 0) {
        int run = 0;
        for (int n = 0; n < Nn; n++) { s_off[n] = run; run += tot[n]; }
        s_off[Nn] = run;
    }
    __syncthreads();

    if (tid < Nn) off[tid] = s_off[tid];
    if (tid == 0) off[Nn] = s_off[Nn];

    for (int e = tid; e < Eg; e += 256) {
        const int d  = dstA[e];
        const int we = e >> 10;
        const int pos = s_off[d] + hist[we][d] + s_loc[e];
        srce[pos] = srcA[e];
        dste[pos] = d;
    }
}

// ---------------- fused weight transpose+split ----------------
__global__ __launch_bounds__(256)
void convT_all_kernel(const float* __restrict__ W1,
                      const float* __restrict__ Wl0, const float* __restrict__ Wr0,
                      const float* __restrict__ Wl1, const float* __restrict__ Wr1,
                      __half* __restrict__ Thi, __half* __restrict__ Tlo) {
    int idx = blockIdx.x * 256 + threadIdx.x;
    if (idx >= WT_TOT) return;
    const float* W; int Kd, loc;
    if (idx < WT_L0)      { W = W1;  Kd = F_IN; loc = idx - WT_W1; }
    else if (idx < WT_R0) { W = Wl0; Kd = HID;  loc = idx - WT_L0; }
    else if (idx < WT_L1) { W = Wr0; Kd = HID;  loc = idx - WT_R0; }
    else if (idx < WT_R1) { W = Wl1; Kd = HID;  loc = idx - WT_L1; }
    else                  { W = Wr1; Kd = HID;  loc = idx - WT_R1; }
    int n = loc / Kd, k = loc % Kd;
    float f = W[(size_t)k * HID + n];
    __half h = __float2half_rn(f);
    Thi[idx] = h;
    Tlo[idx] = __float2half_rn(f - __half2float(h));
}

// ---------------- GEMM (round-9 proven): fp32 A loader-split, fp16-plane weights ----------------
#define PLN 5120
#define HG_SMEM (8*PLN*2)

__global__ __launch_bounds__(256, 2)
void hgemm_kernel(const float* __restrict__ A,
                  const __half* __restrict__ BThi, const __half* __restrict__ BTlo,
                  const float* __restrict__ bias, float* __restrict__ C,
                  const __half* __restrict__ BThi2, const __half* __restrict__ BTlo2,
                  const float* __restrict__ bias2, float* __restrict__ C2,
                  int M, int N, int K,
                  const float* __restrict__ gam, const float* __restrict__ bet,
                  const float* __restrict__ mu,  const float* __restrict__ var,
                  int epi, int dual)
{
    extern __shared__ __half smh[];
    const unsigned smb = (unsigned)__cvta_generic_to_shared(smh);

    const int tid  = threadIdx.x;
    const int warp = tid >> 5;
    const int lane = tid & 31;
    const int gq   = lane >> 2;
    const int tq   = lane & 3;
    int bx = blockIdx.x;
    const int nblk = dual ? (gridDim.x >> 1) : gridDim.x;
    if (dual && bx >= nblk) {
        bx -= nblk;
        BThi = BThi2; BTlo = BTlo2; bias = bias2; C = C2;
    }
    const int cb = bx * 128;
    const int rb = blockIdx.y * 128;

    const int m_w = (warp & 3) * 32;
    const int n_w = (warp >> 2) * 64;

    float acc[2][8][4];
#pragma unroll
    for (int mt = 0; mt < 2; mt++)
#pragma unroll
        for (int nt = 0; nt < 8; nt++)
#pragma unroll
            for (int i = 0; i < 4; i++) acc[mt][nt][i] = 0.f;

    const int lrow = tid >> 1;
    const int seg  = tid & 1;
    const float*  gA  = A    + (size_t)(rb + lrow) * K + seg * 16;
    const __half* gBh = BThi + (size_t)(cb + lrow) * K + seg * 16;
    const __half* gBl = BTlo + (size_t)(cb + lrow) * K + seg * 16;
    const int aoff = lrow * 40 + seg * 16;

    float4 areg[4];

#define LDGA(KC)                                                            \
    {                                                                       \
        _Pragma("unroll")                                                   \
        for (int i = 0; i < 4; i++)                                         \
            areg[i] = *(const float4*)(gA + (KC) + 4*i);                    \
    }

#define CPB(KC, BUF)                                                        \
    {                                                                       \
        const unsigned bh_ = smb + 2u*(4*PLN + (BUF)*PLN + aoff);           \
        const unsigned bl_ = smb + 2u*(6*PLN + (BUF)*PLN + aoff);           \
        cp16(bh_,      gBh + (KC));                                         \
        cp16(bh_ + 16, gBh + (KC) + 8);                                     \
        cp16(bl_,      gBl + (KC));                                         \
        cp16(bl_ + 16, gBl + (KC) + 8);                                     \
        asm volatile("cp.async.commit_group;");                             \
    }

#define STSA(BUF)                                                           \
    {                                                                       \
        uint4 hq, lq;                                                       \
        const unsigned ah_ = smb + 2u*((BUF)*PLN + aoff);                   \
        const unsigned al_ = smb + 2u*(2*PLN + (BUF)*PLN + aoff);           \
        split4(areg[0], hq.x, hq.y, lq.x, lq.y);                            \
        split4(areg[1], hq.z, hq.w, lq.z, lq.w);                            \
        asm volatile("st.shared.v4.b32 [%0], {%1,%2,%3,%4};"                \
            :: "r"(ah_), "r"(hq.x), "r"(hq.y), "r"(hq.z), "r"(hq.w));       \
        asm volatile("st.shared.v4.b32 [%0], {%1,%2,%3,%4};"                \
            :: "r"(al_), "r"(lq.x), "r"(lq.y), "r"(lq.z), "r"(lq.w));       \
        split4(areg[2], hq.x, hq.y, lq.x, lq.y);                            \
        split4(areg[3], hq.z, hq.w, lq.z, lq.w);                            \
        asm volatile("st.shared.v4.b32 [%0], {%1,%2,%3,%4};"                \
            :: "r"(ah_ + 16), "r"(hq.x), "r"(hq.y), "r"(hq.z), "r"(hq.w));  \
        asm volatile("st.shared.v4.b32 [%0], {%1,%2,%3,%4};"                \
            :: "r"(al_ + 16), "r"(lq.x), "r"(lq.y), "r"(lq.z), "r"(lq.w));  \
    }

    LDGA(0);
    CPB(0, 0);
    STSA(0);
    asm volatile("cp.async.wait_group 0;");
    __syncthreads();

    int buf = 0;
    for (int kc = 0; kc < K; kc += 32) {
        const bool last = (kc + 32) >= K;
        if (!last) {
            CPB(kc + 32, buf ^ 1);
            LDGA(kc + 32);
        }

        const int pb = buf * PLN;
#pragma unroll
        for (int k16 = 0; k16 < 32; k16 += 16) {
            unsigned ah[2][4], al[2][4];
#pragma unroll
            for (int mt = 0; mt < 2; mt++) {
                const int r = (m_w + mt*16 + gq) * 40 + k16 + 2*tq;
                ah[mt][0] = *(const unsigned*)&smh[pb + r];
                ah[mt][1] = *(const unsigned*)&smh[pb + r + 320];
                ah[mt][2] = *(const unsigned*)&smh[pb + r + 8];
                ah[mt][3] = *(const unsigned*)&smh[pb + r + 328];
                al[mt][0] = *(const unsigned*)&smh[2*PLN + pb + r];
                al[mt][1] = *(const unsigned*)&smh[2*PLN + pb + r + 320];
                al[mt][2] = *(const unsigned*)&smh[2*PLN + pb + r + 8];
                al[mt][3] = *(const unsigned*)&smh[2*PLN + pb + r + 328];
            }
#pragma unroll
            for (int nt = 0; nt < 8; nt++) {
                const int nb = (n_w + nt*8 + gq) * 40 + k16 + 2*tq;
                unsigned bh[2], bl[2];
                bh[0] = *(const unsigned*)&smh[4*PLN + pb + nb];
                bh[1] = *(const unsigned*)&smh[4*PLN + pb + nb + 8];
                bl[0] = *(const unsigned*)&smh[6*PLN + pb + nb];
                bl[1] = *(const unsigned*)&smh[6*PLN + pb + nb + 8];
#pragma unroll
                for (int mt = 0; mt < 2; mt++) {
                    mma_f16(acc[mt][nt], al[mt], bh);
                    mma_f16(acc[mt][nt], ah[mt], bl);
                    mma_f16(acc[mt][nt], ah[mt], bh);
                }
            }
        }

        if (!last) {
            STSA(buf ^ 1);
            asm volatile("cp.async.wait_group 0;");
            __syncthreads();
            buf ^= 1;
        }
    }

#pragma unroll
    for (int nt = 0; nt < 8; nt++) {
        const int col = cb + n_w + nt*8 + tq*2;
        float s0 = 1.f, s1 = 1.f, t0 = 0.f, t1 = 0.f;
        const float pb0 = bias[col], pb1 = bias[col + 1];
        if (epi == 1) {
            const float i0 = rsqrtf(var[col] + EPSBN);
            const float i1 = rsqrtf(var[col + 1] + EPSBN);
            s0 = gam[col] * i0;     t0 = bet[col]     - mu[col]     * s0;
            s1 = gam[col + 1] * i1; t1 = bet[col + 1] - mu[col + 1] * s1;
        }
#pragma unroll
        for (int mt = 0; mt < 2; mt++) {
            const int r0 = rb + m_w + mt*16 + gq;
#pragma unroll
            for (int half = 0; half < 2; half++) {
                const int r = r0 + half * 8;
                float v0 = acc[mt][nt][half*2 + 0] + pb0;
                float v1 = acc[mt][nt][half*2 + 1] + pb1;
                if (epi == 1) {
                    v0 = gelu_exact(v0 * s0 + t0);
                    v1 = gelu_exact(v1 * s1 + t1);
                }
                *(float2*)&C[(size_t)r * N + col] = make_float2(v0, v1);
            }
        }
    }
#undef LDGA
#undef CPB
#undef STSA
}

// ---------------- fused GATv2 edge kernel (round-5 proven: 122.6 us) ----------------
// grid (HEADS, B), 512 threads, one (sample,head) per block, all data in smem.
#define SM_STRIDE 68
#define GAT_SMEM_FLOATS (2*Nn*SM_STRIDE + 64 + 2*Eg + (Nn+1))
__global__ __launch_bounds__(512)
void gat_kernel(const float* __restrict__ xl, const float* __restrict__ xr,
                const float* __restrict__ att, const float* __restrict__ bo,
                const int* __restrict__ srce, const int* __restrict__ dste,
                const int* __restrict__ off,
                float* __restrict__ out)
{
    extern __shared__ float sm[];
    float*  s_xl   = sm;
    float*  s_xr   = sm + Nn*SM_STRIDE;
    float*  s_att  = sm + 2*Nn*SM_STRIDE;
    float2* s_pair = (float2*)(s_att + 64);
    int*    s_off  = (int*)(s_att + 64 + 2*Eg);

    const int h    = blockIdx.x;
    const int b    = blockIdx.y;
    const int tid  = threadIdx.x;
    const int nthr = 512;

    const float* xlb = xl + (size_t)b * Nn * HID + h * Ch;
    const float* xrb = xr + (size_t)b * Nn * HID + h * Ch;

    for (int i = tid; i < Nn * (Ch/4); i += nthr) {
        int n = i >> 4, c4 = i & 15;
        float4 lv = *(const float4*)(xlb + (size_t)n * HID + 4*c4);
        float4 rv = *(const float4*)(xrb + (size_t)n * HID + 4*c4);
        *(float4*)&s_xl[n*SM_STRIDE + 4*c4] = lv;
        *(float4*)&s_xr[n*SM_STRIDE + 4*c4] = rv;
    }
    if (tid < Ch) s_att[tid] = att[h * Ch + tid];
    if (tid >= nthr - (Nn+1)) s_off[tid - (nthr - (Nn+1))] = off[tid - (nthr - (Nn+1))];
    __syncthreads();

    // ---- phase 1: logits in CSR order (thread per edge) ----
    for (int i = tid; i < Eg; i += nthr) {
        const int s = srce[i];
        const int d = dste[i];
        const float4* pl = (const float4*)&s_xl[s * SM_STRIDE];
        const float4* pr = (const float4*)&s_xr[d * SM_STRIDE];
        float accv = 0.f;
#pragma unroll
        for (int c4 = 0; c4 < 16; c4++) {
            const float4 a4 = *(const float4*)&s_att[4*c4];
            const float4 l4 = pl[c4];
            const float4 r4 = pr[c4];
            float v;
            v = l4.x + r4.x; v = v > 0.f ? v : NEGS * v; accv = fmaf(v, a4.x, accv);
            v = l4.y + r4.y; v = v > 0.f ? v : NEGS * v; accv = fmaf(v, a4.y, accv);
            v = l4.z + r4.z; v = v > 0.f ? v : NEGS * v; accv = fmaf(v, a4.z, accv);
            v = l4.w + r4.w; v = v > 0.f ? v : NEGS * v; accv = fmaf(v, a4.w, accv);
        }
        s_pair[i] = make_float2(accv, __int_as_float(s * SM_STRIDE));
    }
    __syncthreads();

    // ---- phase 2: warp per node; half-warp per edge, float4 channels ----
    const int warp = tid >> 5, lane = tid & 31;
    const int cg = lane & 15;
    const int ep = lane >> 4;
    const float4 bo4 = *(const float4*)(bo + h*Ch + 4*cg);

    for (int n = warp; n < Nn; n += 16) {
        const int o0  = s_off[n];
        const int deg = s_off[n+1] - o0;

        float m = -INFINITY;
        for (int i = lane; i < deg; i += 32) m = fmaxf(m, s_pair[o0 + i].x);
#pragma unroll
        for (int d = 16; d; d >>= 1) m = fmaxf(m, __shfl_xor_sync(0xffffffffu, m, d));

        float ssum = 0.f;
        for (int i = lane; i < deg; i += 32) ssum += expf(s_pair[o0 + i].x - m);
#pragma unroll
        for (int d = 16; d; d >>= 1) ssum += __shfl_xor_sync(0xffffffffu, ssum, d);
        const float inv = 1.0f / (ssum + 1e-16f);

        for (int i = lane; i < deg; i += 32)
            s_pair[o0 + i].x = expf(s_pair[o0 + i].x - m) * inv;
        __syncwarp();

        float4 acc = make_float4(0.f, 0.f, 0.f, 0.f);
#pragma unroll 4
        for (int j = ep; j < deg; j += 2) {
            const float2 p = s_pair[o0 + j];
            const int soff = __float_as_int(p.y);
            const float4 xv = *(const float4*)&s_xl[soff + 4*cg];
            acc.x = fmaf(p.x, xv.x, acc.x);
            acc.y = fmaf(p.x, xv.y, acc.y);
            acc.z = fmaf(p.x, xv.z, acc.z);
            acc.w = fmaf(p.x, xv.w, acc.w);
        }
        acc.x += __shfl_down_sync(0xffffffffu, acc.x, 16);
        acc.y += __shfl_down_sync(0xffffffffu, acc.y, 16);
        acc.z += __shfl_down_sync(0xffffffffu, acc.z, 16);
        acc.w += __shfl_down_sync(0xffffffffu, acc.w, 16);

        if (ep == 0) {
            float4 r;
            r.x = gelu_exact(acc.x + bo4.x);
            r.y = gelu_exact(acc.y + bo4.y);
            r.z = gelu_exact(acc.z + bo4.z);
            r.w = gelu_exact(acc.w + bo4.w);
            *(float4*)(out + (size_t)(b*Nn + n) * HID + h*Ch + 4*cg) = r;
        }
    }
}

// ---------------- fused mean-pool + output proj + BN + gelu ----------------
__global__ __launch_bounds__(256)
void tail_kernel(const float* __restrict__ hin, const float* __restrict__ W2,
                 const float* __restrict__ b2,
                 const float* __restrict__ g2, const float* __restrict__ be2,
                 const float* __restrict__ m2, const float* __restrict__ v2,
                 float* __restrict__ out) {
    const int b = blockIdx.x, c = threadIdx.x;
    __shared__ float sp[HID];
    float s = 0.f;
    const float* base = hin + (size_t)b * Nn * HID + c;
    for (int n = 0; n < Nn; n++) s += base[(size_t)n * HID];
    sp[c] = s * (1.0f / Nn);
    __syncthreads();
    float acc = 0.f;
    for (int k = 0; k < HID; k++) acc = fmaf(sp[k], W2[(size_t)k * HID + c], acc);
    acc += b2[c];
    float inv = rsqrtf(v2[c] + EPSBN);
    acc = (acc - m2[c]) * inv * g2[c] + be2[c];
    out[b * HID + c] = gelu_exact(acc);
}

// ---------------- launch ----------------
extern "C" void kernel_launch(void* const* d_in, const int* in_sizes, int n_in,
                              void* d_out, int out_size) {
    const float* x    = (const float*)d_in[0];
    const int*   ei   = (const int*)  d_in[1];
    const float* W1   = (const float*)d_in[2];
    const float* b1   = (const float*)d_in[3];
    const float* g1   = (const float*)d_in[4];
    const float* be1  = (const float*)d_in[5];
    const float* m1   = (const float*)d_in[6];
    const float* v1   = (const float*)d_in[7];
    const float* Wl0  = (const float*)d_in[8];
    const float* bl0  = (const float*)d_in[9];
    const float* Wr0  = (const float*)d_in[10];
    const float* br0  = (const float*)d_in[11];
    const float* att0 = (const float*)d_in[12];
    const float* bo0  = (const float*)d_in[13];
    const float* Wl1  = (const float*)d_in[14];
    const float* bl1  = (const float*)d_in[15];
    const float* Wr1  = (const float*)d_in[16];
    const float* br1  = (const float*)d_in[17];
    const float* att1 = (const float*)d_in[18];
    const float* bo1  = (const float*)d_in[19];
    const float* W2   = (const float*)d_in[20];
    const float* b2   = (const float*)d_in[21];
    const float* g2   = (const float*)d_in[22];
    const float* be2  = (const float*)d_in[23];
    const float* m2   = (const float*)d_in[24];
    const float* v2   = (const float*)d_in[25];

    float *h, *h2, *xl, *xr;
    int *off, *srce, *dste;
    __half *wthi, *wtlo;
    cudaGetSymbolAddress((void**)&h,    g_h);
    cudaGetSymbolAddress((void**)&h2,   g_h2);
    cudaGetSymbolAddress((void**)&xl,   g_xl);
    cudaGetSymbolAddress((void**)&xr,   g_xr);
    cudaGetSymbolAddress((void**)&off,  g_off);
    cudaGetSymbolAddress((void**)&srce, g_srce);
    cudaGetSymbolAddress((void**)&dste, g_dste);
    cudaGetSymbolAddress((void**)&wthi, g_wthi);
    cudaGetSymbolAddress((void**)&wtlo, g_wtlo);

    const int gat_smem = GAT_SMEM_FLOATS * (int)sizeof(float);   // ~206 KB
    cudaFuncSetAttribute(gat_kernel, cudaFuncAttributeMaxDynamicSharedMemorySize, gat_smem);
    cudaFuncSetAttribute(hgemm_kernel, cudaFuncAttributeMaxDynamicSharedMemorySize, HG_SMEM);

    build_csr_kernel<<<1, 256>>>(ei, off, srce, dste);
    convT_all_kernel<<<(WT_TOT + 255)/256, 256>>>(W1, Wl0, Wr0, Wl1, Wr1, wthi, wtlo);

    // node_proj: h = gelu(BN(x @ W1 + b1))
    hgemm_kernel<<<dim3(HID/128, ROWS/128), 256, HG_SMEM>>>(
        x, wthi + WT_W1, wtlo + WT_W1, b1, h,
        0, 0, 0, 0, ROWS, HID, F_IN, g1, be1, m1, v1, 1, 0);

    // layer 0
    hgemm_kernel<<<dim3(2*HID/128, ROWS/128), 256, HG_SMEM>>>(
        h, wthi + WT_L0, wtlo + WT_L0, bl0, xl,
        wthi + WT_R0, wtlo + WT_R0, br0, xr, ROWS, HID, HID, 0, 0, 0, 0, 0, 1);
    gat_kernel<<<dim3(HEADS, Bsz), 512, gat_smem>>>(xl, xr, att0, bo0, srce, dste, off, h2);

    // layer 1
    hgemm_kernel<<<dim3(2*HID/128, ROWS/128), 256, HG_SMEM>>>(
        h2, wthi + WT_L1, wtlo + WT_L1, bl1, xl,
        wthi + WT_R1, wtlo + WT_R1, br1, xr, ROWS, HID, HID, 0, 0, 0, 0, 0, 1);
    gat_kernel<<<dim3(HEADS, Bsz), 512, gat_smem>>>(xl, xr, att1, bo1, srce, dste, off, h);

    tail_kernel<<<Bsz, 256>>>(h, W2, b2, g2, be2, m2, v2, (float*)d_out);
}

// round 16
// speedup vs baseline: 1.5622x; 1.0006x over previous
#include <cuda_runtime.h>
#include <cuda_fp16.h>
#include <math.h>

// ---------------- problem constants ----------------
#define Bsz   64
#define Nn    256
#define CT    3
#define HID   256
#define HEADS 4
#define Ch    64
#define Eg    8192
#define F_IN  (Nn*CT)
#define ROWS  (Bsz*Nn)
#define NEGS  0.2f
#define EPSBN 1e-5f

// ---------------- scratch ----------------
__device__ float  g_h [ROWS*HID];
__device__ float  g_h2[ROWS*HID];
__device__ float  g_xl[ROWS*HID];
__device__ float  g_xr[ROWS*HID];
__device__ int    g_off[Nn+1];
__device__ int    g_srce[Eg];
__device__ int    g_dste[Eg];
#define WT_W1  0
#define WT_L0  (F_IN*HID)
#define WT_R0  (F_IN*HID + HID*HID)
#define WT_L1  (F_IN*HID + 2*HID*HID)
#define WT_R1  (F_IN*HID + 3*HID*HID)
#define WT_TOT (F_IN*HID + 4*HID*HID)
__device__ __half g_wthi[WT_TOT];
__device__ __half g_wtlo[WT_TOT];

__device__ __forceinline__ float gelu_exact(float x) { return x * normcdff(x); }

__device__ __forceinline__ void mma_f16(float* c, const unsigned* a, const unsigned* b) {
    asm("mma.sync.aligned.m16n8k16.row.col.f32.f16.f16.f32 "
        "{%0,%1,%2,%3},{%4,%5,%6,%7},{%8,%9},{%0,%1,%2,%3};"
        : "+f"(c[0]), "+f"(c[1]), "+f"(c[2]), "+f"(c[3])
        : "r"(a[0]), "r"(a[1]), "r"(a[2]), "r"(a[3]), "r"(b[0]), "r"(b[1]));
}

__device__ __forceinline__ void cp16(unsigned saddr, const void* g) {
    asm volatile("cp.async.cg.shared.global [%0], [%1], 16;" :: "r"(saddr), "l"(g));
}

__device__ __forceinline__ void split4(float4 f, unsigned& h0, unsigned& h1,
                                       unsigned& l0, unsigned& l1) {
    __half2 a = __float22half2_rn(make_float2(f.x, f.y));
    __half2 b = __float22half2_rn(make_float2(f.z, f.w));
    float2 fa = __half22float2(a);
    float2 fb = __half22float2(b);
    __half2 c = __float22half2_rn(make_float2(f.x - fa.x, f.y - fa.y));
    __half2 d = __float22half2_rn(make_float2(f.z - fb.x, f.w - fb.y));
    h0 = *(unsigned*)&a; h1 = *(unsigned*)&b;
    l0 = *(unsigned*)&c; l1 = *(unsigned*)&d;
}

// ---------------- deterministic CSR build (srce + dste) ----------------
__global__ __launch_bounds__(256)
void build_csr_kernel(const int* __restrict__ ei,
                      int* __restrict__ off,
                      int* __restrict__ srce, int* __restrict__ dste) {
    __shared__ int hist[8][Nn];
    __shared__ int s_loc[Eg];
    __shared__ int s_off[Nn+1];

    const int tid  = threadIdx.x;
    const int w    = tid >> 5;
    const int lane = tid & 31;
    const int* srcA = ei;
    const int* dstA = ei + Eg;

    for (int i = tid; i < 8 * Nn; i += 256) ((int*)hist)[i] = 0;
    __syncthreads();

    const int base = w * 1024;
#pragma unroll 1
    for (int g = 0; g < 32; g++) {
        const int e = base + g * 32 + lane;
        const int d = dstA[e];
        unsigned mask = __match_any_sync(0xffffffffu, d);
        int leader = __ffs(mask) - 1;
        int rank   = __popc(mask & ((1u << lane) - 1u));
        int cur    = hist[w][d];
        s_loc[e]   = cur + rank;
        __syncwarp();
        if (lane == leader) hist[w][d] = cur + __popc(mask);
        __syncwarp();
    }
    __syncthreads();

    __shared__ int tot[Nn];
    if (tid < Nn) {
        int run = 0;
#pragma unroll
        for (int ww = 0; ww < 8; ww++) {
            int c = hist[ww][tid];
            hist[ww][tid] = run;
            run += c;
        }
        tot[tid] = run;
    }
    __syncthreads();
    if (tid == 0) {
        int run = 0;
        for (int n = 0; n < Nn; n++) { s_off[n] = run; run += tot[n]; }
        s_off[Nn] = run;
    }
    __syncthreads();

    if (tid < Nn) off[tid] = s_off[tid];
    if (tid == 0) off[Nn] = s_off[Nn];

    for (int e = tid; e < Eg; e += 256) {
        const int d  = dstA[e];
        const int we = e >> 10;
        const int pos = s_off[d] + hist[we][d] + s_loc[e];
        srce[pos] = srcA[e];
        dste[pos] = d;
    }
}

// ---------------- fused weight transpose+split ----------------
__global__ __launch_bounds__(256)
void convT_all_kernel(const float* __restrict__ W1,
                      const float* __restrict__ Wl0, const float* __restrict__ Wr0,
                      const float* __restrict__ Wl1, const float* __restrict__ Wr1,
                      __half* __restrict__ Thi, __half* __restrict__ Tlo) {
    int idx = blockIdx.x * 256 + threadIdx.x;
    if (idx >= WT_TOT) return;
    const float* W; int Kd, loc;
    if (idx < WT_L0)      { W = W1;  Kd = F_IN; loc = idx - WT_W1; }
    else if (idx < WT_R0) { W = Wl0; Kd = HID;  loc = idx - WT_L0; }
    else if (idx < WT_L1) { W = Wr0; Kd = HID;  loc = idx - WT_R0; }
    else if (idx < WT_R1) { W = Wl1; Kd = HID;  loc = idx - WT_L1; }
    else                  { W = Wr1; Kd = HID;  loc = idx - WT_R1; }
    int n = loc / Kd, k = loc % Kd;
    float f = W[(size_t)k * HID + n];
    __half h = __float2half_rn(f);
    Thi[idx] = h;
    Tlo[idx] = __float2half_rn(f - __half2float(h));
}

// ---------------- GEMM (round-9 proven): fp32 A loader-split, fp16-plane weights ----------------
#define PLN 5120
#define HG_SMEM (8*PLN*2)

__global__ __launch_bounds__(256, 2)
void hgemm_kernel(const float* __restrict__ A,
                  const __half* __restrict__ BThi, const __half* __restrict__ BTlo,
                  const float* __restrict__ bias, float* __restrict__ C,
                  const __half* __restrict__ BThi2, const __half* __restrict__ BTlo2,
                  const float* __restrict__ bias2, float* __restrict__ C2,
                  int M, int N, int K,
                  const float* __restrict__ gam, const float* __restrict__ bet,
                  const float* __restrict__ mu,  const float* __restrict__ var,
                  int epi, int dual)
{
    extern __shared__ __half smh[];
    const unsigned smb = (unsigned)__cvta_generic_to_shared(smh);

    const int tid  = threadIdx.x;
    const int warp = tid >> 5;
    const int lane = tid & 31;
    const int gq   = lane >> 2;
    const int tq   = lane & 3;
    int bx = blockIdx.x;
    const int nblk = dual ? (gridDim.x >> 1) : gridDim.x;
    if (dual && bx >= nblk) {
        bx -= nblk;
        BThi = BThi2; BTlo = BTlo2; bias = bias2; C = C2;
    }
    const int cb = bx * 128;
    const int rb = blockIdx.y * 128;

    const int m_w = (warp & 3) * 32;
    const int n_w = (warp >> 2) * 64;

    float acc[2][8][4];
#pragma unroll
    for (int mt = 0; mt < 2; mt++)
#pragma unroll
        for (int nt = 0; nt < 8; nt++)
#pragma unroll
            for (int i = 0; i < 4; i++) acc[mt][nt][i] = 0.f;

    const int lrow = tid >> 1;
    const int seg  = tid & 1;
    const float*  gA  = A    + (size_t)(rb + lrow) * K + seg * 16;
    const __half* gBh = BThi + (size_t)(cb + lrow) * K + seg * 16;
    const __half* gBl = BTlo + (size_t)(cb + lrow) * K + seg * 16;
    const int aoff = lrow * 40 + seg * 16;

    float4 areg[4];

#define LDGA(KC)                                                            \
    {                                                                       \
        _Pragma("unroll")                                                   \
        for (int i = 0; i < 4; i++)                                         \
            areg[i] = *(const float4*)(gA + (KC) + 4*i);                    \
    }

#define CPB(KC, BUF)                                                        \
    {                                                                       \
        const unsigned bh_ = smb + 2u*(4*PLN + (BUF)*PLN + aoff);           \
        const unsigned bl_ = smb + 2u*(6*PLN + (BUF)*PLN + aoff);           \
        cp16(bh_,      gBh + (KC));                                         \
        cp16(bh_ + 16, gBh + (KC) + 8);                                     \
        cp16(bl_,      gBl + (KC));                                         \
        cp16(bl_ + 16, gBl + (KC) + 8);                                     \
        asm volatile("cp.async.commit_group;");                             \
    }

#define STSA(BUF)                                                           \
    {                                                                       \
        uint4 hq, lq;                                                       \
        const unsigned ah_ = smb + 2u*((BUF)*PLN + aoff);                   \
        const unsigned al_ = smb + 2u*(2*PLN + (BUF)*PLN + aoff);           \
        split4(areg[0], hq.x, hq.y, lq.x, lq.y);                            \
        split4(areg[1], hq.z, hq.w, lq.z, lq.w);                            \
        asm volatile("st.shared.v4.b32 [%0], {%1,%2,%3,%4};"                \
            :: "r"(ah_), "r"(hq.x), "r"(hq.y), "r"(hq.z), "r"(hq.w));       \
        asm volatile("st.shared.v4.b32 [%0], {%1,%2,%3,%4};"                \
            :: "r"(al_), "r"(lq.x), "r"(lq.y), "r"(lq.z), "r"(lq.w));       \
        split4(areg[2], hq.x, hq.y, lq.x, lq.y);                            \
        split4(areg[3], hq.z, hq.w, lq.z, lq.w);                            \
        asm volatile("st.shared.v4.b32 [%0], {%1,%2,%3,%4};"                \
            :: "r"(ah_ + 16), "r"(hq.x), "r"(hq.y), "r"(hq.z), "r"(hq.w));  \
        asm volatile("st.shared.v4.b32 [%0], {%1,%2,%3,%4};"                \
            :: "r"(al_ + 16), "r"(lq.x), "r"(lq.y), "r"(lq.z), "r"(lq.w));  \
    }

    LDGA(0);
    CPB(0, 0);
    STSA(0);
    asm volatile("cp.async.wait_group 0;");
    __syncthreads();

    int buf = 0;
    for (int kc = 0; kc < K; kc += 32) {
        const bool last = (kc + 32) >= K;
        if (!last) {
            CPB(kc + 32, buf ^ 1);
            LDGA(kc + 32);
        }

        const int pb = buf * PLN;
#pragma unroll
        for (int k16 = 0; k16 < 32; k16 += 16) {
            unsigned ah[2][4], al[2][4];
#pragma unroll
            for (int mt = 0; mt < 2; mt++) {
                const int r = (m_w + mt*16 + gq) * 40 + k16 + 2*tq;
                ah[mt][0] = *(const unsigned*)&smh[pb + r];
                ah[mt][1] = *(const unsigned*)&smh[pb + r + 320];
                ah[mt][2] = *(const unsigned*)&smh[pb + r + 8];
                ah[mt][3] = *(const unsigned*)&smh[pb + r + 328];
                al[mt][0] = *(const unsigned*)&smh[2*PLN + pb + r];
                al[mt][1] = *(const unsigned*)&smh[2*PLN + pb + r + 320];
                al[mt][2] = *(const unsigned*)&smh[2*PLN + pb + r + 8];
                al[mt][3] = *(const unsigned*)&smh[2*PLN + pb + r + 328];
            }
#pragma unroll
            for (int nt = 0; nt < 8; nt++) {
                const int nb = (n_w + nt*8 + gq) * 40 + k16 + 2*tq;
                unsigned bh[2], bl[2];
                bh[0] = *(const unsigned*)&smh[4*PLN + pb + nb];
                bh[1] = *(const unsigned*)&smh[4*PLN + pb + nb + 8];
                bl[0] = *(const unsigned*)&smh[6*PLN + pb + nb];
                bl[1] = *(const unsigned*)&smh[6*PLN + pb + nb + 8];
#pragma unroll
                for (int mt = 0; mt < 2; mt++) {
                    mma_f16(acc[mt][nt], al[mt], bh);
                    mma_f16(acc[mt][nt], ah[mt], bl);
                    mma_f16(acc[mt][nt], ah[mt], bh);
                }
            }
        }

        if (!last) {
            STSA(buf ^ 1);
            asm volatile("cp.async.wait_group 0;");
            __syncthreads();
            buf ^= 1;
        }
    }

#pragma unroll
    for (int nt = 0; nt < 8; nt++) {
        const int col = cb + n_w + nt*8 + tq*2;
        float s0 = 1.f, s1 = 1.f, t0 = 0.f, t1 = 0.f;
        const float pb0 = bias[col], pb1 = bias[col + 1];
        if (epi == 1) {
            const float i0 = rsqrtf(var[col] + EPSBN);
            const float i1 = rsqrtf(var[col + 1] + EPSBN);
            s0 = gam[col] * i0;     t0 = bet[col]     - mu[col]     * s0;
            s1 = gam[col + 1] * i1; t1 = bet[col + 1] - mu[col + 1] * s1;
        }
#pragma unroll
        for (int mt = 0; mt < 2; mt++) {
            const int r0 = rb + m_w + mt*16 + gq;
#pragma unroll
            for (int half = 0; half < 2; half++) {
                const int r = r0 + half * 8;
                float v0 = acc[mt][nt][half*2 + 0] + pb0;
                float v1 = acc[mt][nt][half*2 + 1] + pb1;
                if (epi == 1) {
                    v0 = gelu_exact(v0 * s0 + t0);
                    v1 = gelu_exact(v1 * s1 + t1);
                }
                *(float2*)&C[(size_t)r * N + col] = make_float2(v0, v1);
            }
        }
    }
#undef LDGA
#undef CPB
#undef STSA
}

// ---------------- fused GATv2 edge kernel (round-5 proven: 122.6 us) ----------------
// grid (HEADS, B), 512 threads, one (sample,head) per block, all data in smem.
#define SM_STRIDE 68
#define GAT_SMEM_FLOATS (2*Nn*SM_STRIDE + 64 + 2*Eg + (Nn+1))
__global__ __launch_bounds__(512)
void gat_kernel(const float* __restrict__ xl, const float* __restrict__ xr,
                const float* __restrict__ att, const float* __restrict__ bo,
                const int* __restrict__ srce, const int* __restrict__ dste,
                const int* __restrict__ off,
                float* __restrict__ out)
{
    extern __shared__ float sm[];
    float*  s_xl   = sm;
    float*  s_xr   = sm + Nn*SM_STRIDE;
    float*  s_att  = sm + 2*Nn*SM_STRIDE;
    float2* s_pair = (float2*)(s_att + 64);
    int*    s_off  = (int*)(s_att + 64 + 2*Eg);

    const int h    = blockIdx.x;
    const int b    = blockIdx.y;
    const int tid  = threadIdx.x;
    const int nthr = 512;

    const float* xlb = xl + (size_t)b * Nn * HID + h * Ch;
    const float* xrb = xr + (size_t)b * Nn * HID + h * Ch;

    for (int i = tid; i < Nn * (Ch/4); i += nthr) {
        int n = i >> 4, c4 = i & 15;
        float4 lv = *(const float4*)(xlb + (size_t)n * HID + 4*c4);
        float4 rv = *(const float4*)(xrb + (size_t)n * HID + 4*c4);
        *(float4*)&s_xl[n*SM_STRIDE + 4*c4] = lv;
        *(float4*)&s_xr[n*SM_STRIDE + 4*c4] = rv;
    }
    if (tid < Ch) s_att[tid] = att[h * Ch + tid];
    if (tid >= nthr - (Nn+1)) s_off[tid - (nthr - (Nn+1))] = off[tid - (nthr - (Nn+1))];
    __syncthreads();

    // ---- phase 1: logits in CSR order (thread per edge) ----
    for (int i = tid; i < Eg; i += nthr) {
        const int s = srce[i];
        const int d = dste[i];
        const float4* pl = (const float4*)&s_xl[s * SM_STRIDE];
        const float4* pr = (const float4*)&s_xr[d * SM_STRIDE];
        float accv = 0.f;
#pragma unroll
        for (int c4 = 0; c4 < 16; c4++) {
            const float4 a4 = *(const float4*)&s_att[4*c4];
            const float4 l4 = pl[c4];
            const float4 r4 = pr[c4];
            float v;
            v = l4.x + r4.x; v = v > 0.f ? v : NEGS * v; accv = fmaf(v, a4.x, accv);
            v = l4.y + r4.y; v = v > 0.f ? v : NEGS * v; accv = fmaf(v, a4.y, accv);
            v = l4.z + r4.z; v = v > 0.f ? v : NEGS * v; accv = fmaf(v, a4.z, accv);
            v = l4.w + r4.w; v = v > 0.f ? v : NEGS * v; accv = fmaf(v, a4.w, accv);
        }
        s_pair[i] = make_float2(accv, __int_as_float(s * SM_STRIDE));
    }
    __syncthreads();

    // ---- phase 2: warp per node; half-warp per edge, float4 channels ----
    const int warp = tid >> 5, lane = tid & 31;
    const int cg = lane & 15;
    const int ep = lane >> 4;
    const float4 bo4 = *(const float4*)(bo + h*Ch + 4*cg);

    for (int n = warp; n < Nn; n += 16) {
        const int o0  = s_off[n];
        const int deg = s_off[n+1] - o0;

        float m = -INFINITY;
        for (int i = lane; i < deg; i += 32) m = fmaxf(m, s_pair[o0 + i].x);
#pragma unroll
        for (int d = 16; d; d >>= 1) m = fmaxf(m, __shfl_xor_sync(0xffffffffu, m, d));

        float ssum = 0.f;
        for (int i = lane; i < deg; i += 32) ssum += expf(s_pair[o0 + i].x - m);
#pragma unroll
        for (int d = 16; d; d >>= 1) ssum += __shfl_xor_sync(0xffffffffu, ssum, d);
        const float inv = 1.0f / (ssum + 1e-16f);

        for (int i = lane; i < deg; i += 32)
            s_pair[o0 + i].x = expf(s_pair[o0 + i].x - m) * inv;
        __syncwarp();

        float4 acc = make_float4(0.f, 0.f, 0.f, 0.f);
#pragma unroll 4
        for (int j = ep; j < deg; j += 2) {
            const float2 p = s_pair[o0 + j];
            const int soff = __float_as_int(p.y);
            const float4 xv = *(const float4*)&s_xl[soff + 4*cg];
            acc.x = fmaf(p.x, xv.x, acc.x);
            acc.y = fmaf(p.x, xv.y, acc.y);
            acc.z = fmaf(p.x, xv.z, acc.z);
            acc.w = fmaf(p.x, xv.w, acc.w);
        }
        acc.x += __shfl_down_sync(0xffffffffu, acc.x, 16);
        acc.y += __shfl_down_sync(0xffffffffu, acc.y, 16);
        acc.z += __shfl_down_sync(0xffffffffu, acc.z, 16);
        acc.w += __shfl_down_sync(0xffffffffu, acc.w, 16);

        if (ep == 0) {
            float4 r;
            r.x = gelu_exact(acc.x + bo4.x);
            r.y = gelu_exact(acc.y + bo4.y);
            r.z = gelu_exact(acc.z + bo4.z);
            r.w = gelu_exact(acc.w + bo4.w);
            *(float4*)(out + (size_t)(b*Nn + n) * HID + h*Ch + 4*cg) = r;
        }
    }
}

// ---------------- fused mean-pool + output proj + BN + gelu ----------------
__global__ __launch_bounds__(256)
void tail_kernel(const float* __restrict__ hin, const float* __restrict__ W2,
                 const float* __restrict__ b2,
                 const float* __restrict__ g2, const float* __restrict__ be2,
                 const float* __restrict__ m2, const float* __restrict__ v2,
                 float* __restrict__ out) {
    const int b = blockIdx.x, c = threadIdx.x;
    __shared__ float sp[HID];
    float s = 0.f;
    const float* base = hin + (size_t)b * Nn * HID + c;
    for (int n = 0; n < Nn; n++) s += base[(size_t)n * HID];
    sp[c] = s * (1.0f / Nn);
    __syncthreads();
    float acc = 0.f;
    for (int k = 0; k < HID; k++) acc = fmaf(sp[k], W2[(size_t)k * HID + c], acc);
    acc += b2[c];
    float inv = rsqrtf(v2[c] + EPSBN);
    acc = (acc - m2[c]) * inv * g2[c] + be2[c];
    out[b * HID + c] = gelu_exact(acc);
}

// ---------------- launch ----------------
extern "C" void kernel_launch(void* const* d_in, const int* in_sizes, int n_in,
                              void* d_out, int out_size) {
    const float* x    = (const float*)d_in[0];
    const int*   ei   = (const int*)  d_in[1];
    const float* W1   = (const float*)d_in[2];
    const float* b1   = (const float*)d_in[3];
    const float* g1   = (const float*)d_in[4];
    const float* be1  = (const float*)d_in[5];
    const float* m1   = (const float*)d_in[6];
    const float* v1   = (const float*)d_in[7];
    const float* Wl0  = (const float*)d_in[8];
    const float* bl0  = (const float*)d_in[9];
    const float* Wr0  = (const float*)d_in[10];
    const float* br0  = (const float*)d_in[11];
    const float* att0 = (const float*)d_in[12];
    const float* bo0  = (const float*)d_in[13];
    const float* Wl1  = (const float*)d_in[14];
    const float* bl1  = (const float*)d_in[15];
    const float* Wr1  = (const float*)d_in[16];
    const float* br1  = (const float*)d_in[17];
    const float* att1 = (const float*)d_in[18];
    const float* bo1  = (const float*)d_in[19];
    const float* W2   = (const float*)d_in[20];
    const float* b2   = (const float*)d_in[21];
    const float* g2   = (const float*)d_in[22];
    const float* be2  = (const float*)d_in[23];
    const float* m2   = (const float*)d_in[24];
    const float* v2   = (const float*)d_in[25];

    float *h, *h2, *xl, *xr;
    int *off, *srce, *dste;
    __half *wthi, *wtlo;
    cudaGetSymbolAddress((void**)&h,    g_h);
    cudaGetSymbolAddress((void**)&h2,   g_h2);
    cudaGetSymbolAddress((void**)&xl,   g_xl);
    cudaGetSymbolAddress((void**)&xr,   g_xr);
    cudaGetSymbolAddress((void**)&off,  g_off);
    cudaGetSymbolAddress((void**)&srce, g_srce);
    cudaGetSymbolAddress((void**)&dste, g_dste);
    cudaGetSymbolAddress((void**)&wthi, g_wthi);
    cudaGetSymbolAddress((void**)&wtlo, g_wtlo);

    const int gat_smem = GAT_SMEM_FLOATS * (int)sizeof(float);   // ~206 KB
    cudaFuncSetAttribute(gat_kernel, cudaFuncAttributeMaxDynamicSharedMemorySize, gat_smem);
    cudaFuncSetAttribute(hgemm_kernel, cudaFuncAttributeMaxDynamicSharedMemorySize, HG_SMEM);

    build_csr_kernel<<<1, 256>>>(ei, off, srce, dste);
    convT_all_kernel<<<(WT_TOT + 255)/256, 256>>>(W1, Wl0, Wr0, Wl1, Wr1, wthi, wtlo);

    // node_proj: h = gelu(BN(x @ W1 + b1))
    hgemm_kernel<<<dim3(HID/128, ROWS/128), 256, HG_SMEM>>>(
        x, wthi + WT_W1, wtlo + WT_W1, b1, h,
        0, 0, 0, 0, ROWS, HID, F_IN, g1, be1, m1, v1, 1, 0);

    // layer 0
    hgemm_kernel<<<dim3(2*HID/128, ROWS/128), 256, HG_SMEM>>>(
        h, wthi + WT_L0, wtlo + WT_L0, bl0, xl,
        wthi + WT_R0, wtlo + WT_R0, br0, xr, ROWS, HID, HID, 0, 0, 0, 0, 0, 1);
    gat_kernel<<<dim3(HEADS, Bsz), 512, gat_smem>>>(xl, xr, att0, bo0, srce, dste, off, h2);

    // layer 1
    hgemm_kernel<<<dim3(2*HID/128, ROWS/128), 256, HG_SMEM>>>(
        h2, wthi + WT_L1, wtlo + WT_L1, bl1, xl,
        wthi + WT_R1, wtlo + WT_R1, br1, xr, ROWS, HID, HID, 0, 0, 0, 0, 0, 1);
    gat_kernel<<<dim3(HEADS, Bsz), 512, gat_smem>>>(xl, xr, att1, bo1, srce, dste, off, h);

    tail_kernel<<<Bsz, 256>>>(h, W2, b2, g2, be2, m2, v2, (float*)d_out);
}